// round 9
// baseline (speedup 1.0000x reference)
#include <cuda_runtime.h>
#include <cstdint>

// out[b,k,oc,x] = sum_ci W[k,oc,ci]*in[b,ci,k,x] + bias[k,oc]
// in: [4096,128,9,9]  w: [9,128,128]  bias: [9,128]  out: [4096,9,128,9] (f32)
//
// Warp-specialized tf32 mma.sync pipeline:
//   8 consumer warps: 16x72 warp tile (M=128 oc, N=72 = 8 batches), K=128
//   4 producer warps: cp.async (LDGSTS, 4B) -> smem, quad-buffered at quarter-K (32 ci)
// X enters as raw f32 bits (tf32 truncation in MMA); W is cvt.rna'd at staging.
// W staged once per CTA, reused over 16 tiles. grid=(9,32) -> 1 wave @ 2 CTA/SM.

#define KK     9
#define CIN    128
#define COUT   128
#define NB     8
#define TILES  16
#define NTHR   384
#define NCONS  256          // consumer threads (warps 0..7)
#define NBUF   4            // quarter-K buffers

#define SWS 132             // sW stride: A-frag banks (4g+t) perfect
#define SXS 72              // buffer stride: B-frag banks (8t+8nt+g) perfect
#define XQ_WORDS (32 * SXS)             // 2304 words per quarter (9216 B)
#define SW_BYTES (128 * SWS * 4)        // 67584
#define SMEM_BYTES (SW_BYTES + NBUF * XQ_WORDS * 4)   // 104448 -> 2 CTAs/SM

// named barriers: full[q] = 1+q, empty[q] = 5+q
#define BAR_ARRIVE(id) asm volatile("bar.arrive %0, %1;" :: "r"(id), "r"(NTHR) : "memory")
#define BAR_SYNC(id)   asm volatile("bar.sync %0, %1;"   :: "r"(id), "r"(NTHR) : "memory")

__device__ __forceinline__ uint32_t f2tf32(float f) {
    uint32_t u;
    asm("cvt.rna.tf32.f32 %0, %1;" : "=r"(u) : "f"(f));
    return u;
}
__device__ __forceinline__ uint32_t smem_u32(const void* p) {
    uint32_t a;
    asm("{ .reg .u64 t; cvta.to.shared.u64 t, %1; cvt.u32.u64 %0, t; }" : "=r"(a) : "l"(p));
    return a;
}
__device__ __forceinline__ void cp4(uint32_t dst, const float* src) {
    asm volatile("cp.async.ca.shared.global [%0], [%1], 4;" :: "r"(dst), "l"(src));
}

__device__ __forceinline__ void mma_tf32(float* d, const uint32_t* a, const uint32_t* b) {
    asm volatile(
        "mma.sync.aligned.m16n8k8.row.col.f32.tf32.tf32.f32 "
        "{%0,%1,%2,%3}, {%4,%5,%6,%7}, {%8,%9}, {%0,%1,%2,%3};"
        : "+f"(d[0]), "+f"(d[1]), "+f"(d[2]), "+f"(d[3])
        : "r"(a[0]), "r"(a[1]), "r"(a[2]), "r"(a[3]), "r"(b[0]), "r"(b[1]));
}

__global__ void __launch_bounds__(NTHR, 2)
gather_vertical_ws(const float* __restrict__ in,
                   const float* __restrict__ w,
                   const float* __restrict__ bias,
                   float* __restrict__ out)
{
    extern __shared__ char smem[];
    uint32_t* sW = reinterpret_cast<uint32_t*>(smem);             // [oc][ci], stride SWS
    uint32_t* sX = reinterpret_cast<uint32_t*>(smem + SW_BYTES);  // 4 quarters [32][72]

    const int tid = threadIdx.x;
    const int k   = blockIdx.x;
    const int yid = blockIdx.y;
    const int bbase = yid * TILES * NB;              // first batch of this CTA

    // ---- stage W[k] once, rna-rounded (all 384 threads) ----
    {
        const float* wk = w + k * COUT * CIN;
        #pragma unroll 4
        for (int i = tid; i < COUT * CIN; i += NTHR) {
            int oc = i >> 7, ci = i & 127;
            sW[oc * SWS + ci] = f2tf32(wk[i]);
        }
    }
    __syncthreads();

    if (tid >= NCONS) {
        // =================== PRODUCER (4 warps, 128 threads) ===================
        const int ptid = tid - NCONS;
        const float* src = in + (size_t)bbase * (CIN * 81) + (size_t)k * 9;
        const uint32_t sx_base = smem_u32(smem) + SW_BYTES;

        // loop-invariant per-thread offsets (18 elements per quarter)
        int goff[18];      // gmem float offset within quarter block
        int soff[18];      // smem byte offset within quarter buffer
        #pragma unroll
        for (int j = 0; j < 18; j++) {
            int e  = ptid + 128 * j;     // 0..2303
            int q  = e / 9;              // bl*32 + ci_local
            int x  = e - 9 * q;
            int bl = q >> 5;
            int ci = q & 31;
            goff[j] = (bl * CIN + ci) * 81 + x;
            soff[j] = (ci * SXS + bl * 9 + x) * 4;
        }

        for (int s = 0; s < NBUF * TILES; s++) {
            const int qi = s & 3;                     // quarter == buffer
            const int t  = s >> 2;
            if (s >= NBUF) BAR_SYNC(5 + qi);          // wait consumers done with buf

            const float* st = src + (size_t)(t * NB) * (CIN * 81) + qi * 32 * 81;
            const uint32_t db = sx_base + qi * (XQ_WORDS * 4);
            #pragma unroll
            for (int j = 0; j < 18; j++)
                cp4(db + soff[j], st + goff[j]);
            asm volatile("cp.async.commit_group;" ::: "memory");

            if (s >= 1) {
                asm volatile("cp.async.wait_group 1;" ::: "memory");
                asm volatile("fence.acq_rel.cta;" ::: "memory");
                BAR_ARRIVE(1 + ((s - 1) & 3));        // previous quarter now full
            }
        }
        asm volatile("cp.async.wait_group 0;" ::: "memory");
        asm volatile("fence.acq_rel.cta;" ::: "memory");
        BAR_ARRIVE(1 + 3);                            // last quarter (s=63, buf 3)
    } else {
        // =================== CONSUMER (8 warps, 256 threads) ===================
        const int wid  = tid >> 5, lane = tid & 31;
        const int g    = lane >> 2, tl = lane & 3;
        const int oc0  = wid * 16;
        const int r0   = oc0 + g, r1 = r0 + 8;
        const float bv0 = bias[k * COUT + r0];
        const float bv1 = bias[k * COUT + r1];

        for (int t = 0; t < TILES; t++) {
            float d[9][4];
            #pragma unroll
            for (int nt = 0; nt < 9; nt++)
                #pragma unroll
                for (int j = 0; j < 4; j++) d[nt][j] = 0.0f;

            #pragma unroll
            for (int qi = 0; qi < NBUF; qi++) {
                BAR_SYNC(1 + qi);                     // wait buf qi full

                const uint32_t* pa0 = sW + r0 * SWS + qi * 32 + tl;
                const uint32_t* pa1 = sW + r1 * SWS + qi * 32 + tl;
                const uint32_t* pb  = sX + qi * XQ_WORDS + tl * SXS + g;

                #pragma unroll
                for (int ks = 0; ks < 4; ks++) {
                    uint32_t a[4];
                    a[0] = pa0[0];
                    a[1] = pa1[0];
                    a[2] = pa0[4];
                    a[3] = pa1[4];

                    uint32_t b[9][2];
                    #pragma unroll
                    for (int nt = 0; nt < 9; nt++) {
                        b[nt][0] = pb[nt * 8];
                        b[nt][1] = pb[4 * SXS + nt * 8];
                    }
                    #pragma unroll
                    for (int nt = 0; nt < 9; nt++)
                        mma_tf32(d[nt], a, b[nt]);

                    pa0 += 8; pa1 += 8; pb += 8 * SXS;
                }
                BAR_ARRIVE(5 + qi);                   // release buf qi
            }

            // ---- epilogue: direct STG (overlaps producer fill of next tile) ----
            float* ob = out + ((size_t)(bbase + t * NB) * 9 + k) * 1152;
            #pragma unroll
            for (int nt = 0; nt < 9; nt++) {
                int n   = nt * 8 + 2 * tl;
                int b0q = n / 9,       x0 = n - 9 * b0q;
                int b1q = (n + 1) / 9, x1 = (n + 1) - 9 * b1q;
                float* c0 = ob + (size_t)b0q * 10368;
                float* c1 = ob + (size_t)b1q * 10368;
                c0[r0 * 9 + x0] = d[nt][0] + bv0;
                c1[r0 * 9 + x1] = d[nt][1] + bv0;
                c0[r1 * 9 + x0] = d[nt][2] + bv1;
                c1[r1 * 9 + x1] = d[nt][3] + bv1;
            }
        }
    }
}

extern "C" void kernel_launch(void* const* d_in, const int* in_sizes, int n_in,
                              void* d_out, int out_size)
{
    const float* in   = (const float*)d_in[0];
    const float* w    = (const float*)d_in[1];
    const float* bias = (const float*)d_in[2];
    float* out        = (float*)d_out;

    int B = in_sizes[0] / (CIN * 81);        // 4096

    cudaFuncSetAttribute(gather_vertical_ws,
                         cudaFuncAttributeMaxDynamicSharedMemorySize, SMEM_BYTES);

    dim3 grid(KK, B / (NB * TILES));         // (9, 32)
    gather_vertical_ws<<<grid, NTHR, SMEM_BYTES>>>(in, w, bias, out);
}

// round 10
// speedup vs baseline: 1.0297x; 1.0297x over previous
#include <cuda_runtime.h>
#include <cstdint>

// out[b,k,oc,x] = sum_ci W[k,oc,ci]*in[b,ci,k,x] + bias[k,oc]
// in: [4096,128,9,9]  w: [9,128,128]  bias: [9,128]  out: [4096,9,128,9] (f32)
//
// All-consumer multi-stage cp.async pipeline (no warp specialization):
//   256 threads = 8 warps, warp tile 16x72 (M=128 oc, N=72 = 8 batches), K=128
//   4 quarter-K smem stages (32 ci x 72 n), cp.async 3 stages ahead, wait_group 2.
// X enters as raw f32 bits (tf32 truncation in MMA); W is cvt.rna'd at staging.
// W staged once per CTA, reused over 16 tiles. grid=(9,32) -> 1 wave @ 2 CTA/SM.

#define KK     9
#define CIN    128
#define COUT   128
#define NB     8
#define TILES  16
#define NTHR   256
#define NBUF   4            // quarter-K stages
#define NSTEP  (NBUF * TILES)   // 64 quarters per CTA

#define SWS 132             // sW stride: A-frag banks (4g+t) perfect
#define SXS 72              // stage stride: B-frag banks (8t+8nt+g) perfect
#define XQ_WORDS (32 * SXS)             // 2304 words per quarter (9216 B)
#define SW_BYTES (128 * SWS * 4)        // 67584
#define SMEM_BYTES (SW_BYTES + NBUF * XQ_WORDS * 4)   // 104448 -> 2 CTAs/SM

__device__ __forceinline__ uint32_t f2tf32(float f) {
    uint32_t u;
    asm("cvt.rna.tf32.f32 %0, %1;" : "=r"(u) : "f"(f));
    return u;
}
__device__ __forceinline__ uint32_t smem_u32(const void* p) {
    uint32_t a;
    asm("{ .reg .u64 t; cvta.to.shared.u64 t, %1; cvt.u32.u64 %0, t; }" : "=r"(a) : "l"(p));
    return a;
}
__device__ __forceinline__ void cp4(uint32_t dst, const float* src) {
    asm volatile("cp.async.ca.shared.global [%0], [%1], 4;" :: "r"(dst), "l"(src));
}
__device__ __forceinline__ void mma_tf32(float* d, const uint32_t* a, const uint32_t* b) {
    asm volatile(
        "mma.sync.aligned.m16n8k8.row.col.f32.tf32.tf32.f32 "
        "{%0,%1,%2,%3}, {%4,%5,%6,%7}, {%8,%9}, {%0,%1,%2,%3};"
        : "+f"(d[0]), "+f"(d[1]), "+f"(d[2]), "+f"(d[3])
        : "r"(a[0]), "r"(a[1]), "r"(a[2]), "r"(a[3]), "r"(b[0]), "r"(b[1]));
}

__global__ void __launch_bounds__(NTHR, 2)
gather_vertical_ms(const float* __restrict__ in,
                   const float* __restrict__ w,
                   const float* __restrict__ bias,
                   float* __restrict__ out)
{
    extern __shared__ char smem[];
    uint32_t* sW = reinterpret_cast<uint32_t*>(smem);             // [oc][ci], stride SWS
    uint32_t* sX = reinterpret_cast<uint32_t*>(smem + SW_BYTES);  // 4 stages [32][72]

    const int tid = threadIdx.x;
    const int k   = blockIdx.x;
    const int yid = blockIdx.y;
    const int bbase = yid * TILES * NB;

    // ---- stage W[k] once, rna-rounded ----
    {
        const float* wk = w + k * COUT * CIN;
        #pragma unroll 4
        for (int i = tid; i < COUT * CIN; i += NTHR) {
            int oc = i >> 7, ci = i & 127;
            sW[oc * SWS + ci] = f2tf32(wk[i]);
        }
    }

    // ---- per-thread cp.async offsets (9 elements per stage), loop-invariant ----
    const float* src = in + (size_t)bbase * (CIN * 81) + (size_t)k * 9;
    const uint32_t sx_base = smem_u32(smem) + SW_BYTES;
    int goff[9], soff[9];
    #pragma unroll
    for (int j = 0; j < 9; j++) {
        int e  = tid + NTHR * j;      // 0..2303
        int q  = e / 9;               // bl*32 + ci_local
        int x  = e - 9 * q;
        int bl = q >> 5;
        int ci = q & 31;
        goff[j] = (bl * CIN + ci) * 81 + x;
        soff[j] = (ci * SXS + bl * 9 + x) * 4;
    }

    // ---- prologue: issue stages 0..2 ----
    #pragma unroll
    for (int s = 0; s < 3; s++) {
        const int t = s >> 2, qi = s & 3;           // t=0 here
        const float* st = src + (size_t)(t * NB) * (CIN * 81) + qi * 32 * 81;
        const uint32_t db = sx_base + qi * (XQ_WORDS * 4);
        #pragma unroll
        for (int j = 0; j < 9; j++) cp4(db + soff[j], st + goff[j]);
        asm volatile("cp.async.commit_group;" ::: "memory");
    }
    __syncthreads();    // W visible

    // ---- consumer identity ----
    const int wid  = tid >> 5, lane = tid & 31;
    const int g    = lane >> 2, tl = lane & 3;
    const int r0   = wid * 16 + g, r1 = r0 + 8;
    const float bv0 = bias[k * COUT + r0];
    const float bv1 = bias[k * COUT + r1];

    float d[9][4];

    for (int s = 0; s < NSTEP; s++) {
        const int qi = s & 3;

        if (qi == 0) {
            #pragma unroll
            for (int nt = 0; nt < 9; nt++)
                #pragma unroll
                for (int j = 0; j < 4; j++) d[nt][j] = 0.0f;
        }

        asm volatile("cp.async.wait_group 2;" ::: "memory");  // stage s arrived
        __syncthreads();

        // issue stage s+3 (buffer (s+3)&3 == (s-1)&3, free after the sync above)
        if (s + 3 < NSTEP) {
            const int sn = s + 3, tn = sn >> 2, qn = sn & 3;
            const float* st = src + (size_t)(tn * NB) * (CIN * 81) + qn * 32 * 81;
            const uint32_t db = sx_base + qn * (XQ_WORDS * 4);
            #pragma unroll
            for (int j = 0; j < 9; j++) cp4(db + soff[j], st + goff[j]);
        }
        asm volatile("cp.async.commit_group;" ::: "memory");  // group (s+3), possibly empty

        // ---- MMA on stage qi: 4 k-steps ----
        {
            const uint32_t* pa0 = sW + r0 * SWS + qi * 32 + tl;
            const uint32_t* pa1 = sW + r1 * SWS + qi * 32 + tl;
            const uint32_t* pb  = sX + qi * XQ_WORDS + tl * SXS + g;

            #pragma unroll
            for (int ks = 0; ks < 4; ks++) {
                uint32_t a[4];
                a[0] = pa0[0];
                a[1] = pa1[0];
                a[2] = pa0[4];
                a[3] = pa1[4];

                uint32_t b[9][2];
                #pragma unroll
                for (int nt = 0; nt < 9; nt++) {
                    b[nt][0] = pb[nt * 8];
                    b[nt][1] = pb[4 * SXS + nt * 8];
                }
                #pragma unroll
                for (int nt = 0; nt < 9; nt++)
                    mma_tf32(d[nt], a, b[nt]);

                pa0 += 8; pa1 += 8; pb += 8 * SXS;
            }
        }

        // ---- tile boundary: epilogue (direct STG, overlaps next stages) ----
        if (qi == 3) {
            const int t = s >> 2;
            float* ob = out + ((size_t)(bbase + t * NB) * 9 + k) * 1152;
            #pragma unroll
            for (int nt = 0; nt < 9; nt++) {
                int n   = nt * 8 + 2 * tl;
                int b0q = n / 9,       x0 = n - 9 * b0q;
                int b1q = (n + 1) / 9, x1 = (n + 1) - 9 * b1q;
                float* c0 = ob + (size_t)b0q * 10368;
                float* c1 = ob + (size_t)b1q * 10368;
                c0[r0 * 9 + x0] = d[nt][0] + bv0;
                c1[r0 * 9 + x1] = d[nt][1] + bv0;
                c0[r1 * 9 + x0] = d[nt][2] + bv1;
                c1[r1 * 9 + x1] = d[nt][3] + bv1;
            }
        }
    }
}

extern "C" void kernel_launch(void* const* d_in, const int* in_sizes, int n_in,
                              void* d_out, int out_size)
{
    const float* in   = (const float*)d_in[0];
    const float* w    = (const float*)d_in[1];
    const float* bias = (const float*)d_in[2];
    float* out        = (float*)d_out;

    int B = in_sizes[0] / (CIN * 81);        // 4096

    cudaFuncSetAttribute(gather_vertical_ms,
                         cudaFuncAttributeMaxDynamicSharedMemorySize, SMEM_BYTES);

    dim3 grid(KK, B / (NB * TILES));         // (9, 32)
    gather_vertical_ms<<<grid, NTHR, SMEM_BYTES>>>(in, w, bias, out);
}